// round 3
// baseline (speedup 1.0000x reference)
#include <cuda_runtime.h>
#include <cstddef>

#define BB 16
#define SS 1024
#define DD 16
#define HH 4
#define DEPTH 4
#define NEGV (-1e9f)

// ---- sizes / output offsets (tuple order: out_mm, w_mm, out_md, w_md, out_dd, w_dd)
#define O_SZ (BB*SS*DD)            // 262144
#define W_SZ ((size_t)BB*HH*SS*SS) // 67108864
#define OFF_OUT_MM ((size_t)0)
#define OFF_W_MM   ((size_t)O_SZ)
#define OFF_OUT_MD (OFF_W_MM + W_SZ)
#define OFF_W_MD   (OFF_OUT_MD + O_SZ)
#define OFF_OUT_DD (OFF_W_MD + W_SZ)
#define OFF_W_DD   (OFF_OUT_DD + O_SZ)

// ---- scratch (no allocations allowed; __device__ globals)
__device__ float4 g_mq[BB*HH*SS], g_mk[BB*HH*SS], g_mv[BB*HH*SS];
__device__ float4 g_dq[BB*HH*SS], g_dk[BB*HH*SS], g_dv[BB*HH*SS];
__device__ float4 g_att_mm[BB*HH*SS], g_att_md[BB*HH*SS], g_att_dd[BB*HH*SS];

// ============================================================================
// Kernel 1: the six 16x16 projections. One thread = one (source,row).
// ============================================================================
__global__ void proj_kernel(const float* __restrict__ med, const float* __restrict__ diag,
                            const float* __restrict__ wmq, const float* __restrict__ bmq,
                            const float* __restrict__ wmk, const float* __restrict__ bmk,
                            const float* __restrict__ wmv, const float* __restrict__ bmv,
                            const float* __restrict__ wdq, const float* __restrict__ bdq,
                            const float* __restrict__ wdk, const float* __restrict__ bdk,
                            const float* __restrict__ wdv, const float* __restrict__ bdv)
{
    __shared__ float sw[6][DD*DD];
    __shared__ float sb[6][DD];
    const float* wp[6] = {wmq, wmk, wmv, wdq, wdk, wdv};
    const float* bp[6] = {bmq, bmk, bmv, bdq, bdk, bdv};
    int tid = threadIdx.x;
    for (int w = 0; w < 6; w++) {
        for (int i = tid; i < DD*DD; i += blockDim.x) sw[w][i] = wp[w][i];
        if (tid < DD) sb[w][tid] = bp[w][tid];
    }
    __syncthreads();

    int gid = blockIdx.x * blockDim.x + tid;   // 0 .. 2*B*S-1
    if (gid >= 2*BB*SS) return;
    int src = (gid >= BB*SS) ? 1 : 0;
    int row = gid - src*BB*SS;                 // b*S + s
    const float* x = (src ? diag : med) + (size_t)row * DD;

    float xv[DD];
    #pragma unroll
    for (int i = 0; i < DD; i++) xv[i] = x[i];

    const float* Wq = sw[src*3 + 0];
    const float* Wk = sw[src*3 + 1];
    const float* Wv = sw[src*3 + 2];
    const float* Bq = sb[src*3 + 0];
    const float* Bk = sb[src*3 + 1];
    const float* Bv = sb[src*3 + 2];

    float yq[DD], yk[DD], yv[DD];
    #pragma unroll
    for (int j = 0; j < DD; j++) {
        float aq = Bq[j], ak = Bk[j], av = Bv[j];
        #pragma unroll
        for (int i = 0; i < DD; i++) {
            float xi = xv[i];
            aq += xi * Wq[i*DD + j];
            ak += xi * Wk[i*DD + j];
            av += xi * Wv[i*DD + j];
        }
        yq[j] = aq; yk[j] = ak; yv[j] = av;
    }

    int b = row / SS, s = row % SS;
    float4* Oq = src ? g_dq : g_mq;
    float4* Ok = src ? g_dk : g_mk;
    float4* Ov = src ? g_dv : g_mv;
    #pragma unroll
    for (int h = 0; h < HH; h++) {
        int idx = (b*HH + h)*SS + s;
        Oq[idx] = make_float4(yq[4*h], yq[4*h+1], yq[4*h+2], yq[4*h+3]);
        Ok[idx] = make_float4(yk[4*h], yk[4*h+1], yk[4*h+2], yk[4*h+3]);
        Ov[idx] = make_float4(yv[4*h], yv[4*h+1], yv[4*h+2], yv[4*h+3]);
    }
}

// ============================================================================
// Kernel 2: fused triple attention. Block = (qtile of 16, h, b), warp = q-row.
// Pass 1: online max+sum for all 3 attentions. Pass 2: recompute logits,
// write normalized+masked weights (the dominant 768 MB of writes), accumulate
// the attention outputs.
// ============================================================================
__global__ __launch_bounds__(512) void attn_kernel(const float* __restrict__ mask,
                                                   float* __restrict__ out)
{
    __shared__ float4 sKm[SS];
    __shared__ float4 sKd[SS];
    __shared__ float4 sVd[SS];

    int qt = blockIdx.x;          // 0..63
    int h  = blockIdx.y;
    int b  = blockIdx.z;
    int bh = b*HH + h;
    int tid = threadIdx.x;

    for (int i = tid; i < SS; i += 512) {
        sKm[i] = g_mk[bh*SS + i];
        sKd[i] = g_dk[bh*SS + i];
        sVd[i] = g_dv[bh*SS + i];
    }
    __syncthreads();

    int warp = tid >> 5, lane = tid & 31;
    int q = qt*16 + warp;

    float4 mq = g_mq[bh*SS + q];
    float4 dq = g_dq[bh*SS + q];
    const float* mrow = mask + ((size_t)b*SS + q)*SS;       // mask[b,q,:]
    const float* mcol = mask + (size_t)b*SS*SS + q;          // mask[b,:,q] stride S

    // ---- pass 1: online softmax stats for mm, md, dd
    float m0 = -1e30f, m1 = -1e30f, m2 = -1e30f;
    float s0 = 0.f, s1 = 0.f, s2 = 0.f;
    #pragma unroll 4
    for (int t = 0; t < 32; t++) {
        int k = t*32 + lane;
        float4 km = sKm[k];
        float4 kd = sKd[k];
        float addm = mrow[k] * NEGV;
        float l0 = 0.5f*(mq.x*km.x + mq.y*km.y + mq.z*km.z + mq.w*km.w) + addm;
        float l1 = 0.5f*(mq.x*kd.x + mq.y*kd.y + mq.z*kd.z + mq.w*kd.w) + addm;
        float l2 = 0.5f*(dq.x*kd.x + dq.y*kd.y + dq.z*kd.z + dq.w*kd.w) + addm;
        float nm;
        nm = fmaxf(m0, l0); s0 = s0*__expf(m0-nm) + __expf(l0-nm); m0 = nm;
        nm = fmaxf(m1, l1); s1 = s1*__expf(m1-nm) + __expf(l1-nm); m1 = nm;
        nm = fmaxf(m2, l2); s2 = s2*__expf(m2-nm) + __expf(l2-nm); m2 = nm;
    }
    // warp-combine (m, s)
    #pragma unroll
    for (int off = 16; off > 0; off >>= 1) {
        float om, os, nm;
        om = __shfl_xor_sync(0xffffffffu, m0, off);
        os = __shfl_xor_sync(0xffffffffu, s0, off);
        nm = fmaxf(m0, om); s0 = s0*__expf(m0-nm) + os*__expf(om-nm); m0 = nm;
        om = __shfl_xor_sync(0xffffffffu, m1, off);
        os = __shfl_xor_sync(0xffffffffu, s1, off);
        nm = fmaxf(m1, om); s1 = s1*__expf(m1-nm) + os*__expf(om-nm); m1 = nm;
        om = __shfl_xor_sync(0xffffffffu, m2, off);
        os = __shfl_xor_sync(0xffffffffu, s2, off);
        nm = fmaxf(m2, om); s2 = s2*__expf(m2-nm) + os*__expf(om-nm); m2 = nm;
    }
    float inv0 = 1.f / s0, inv1 = 1.f / s1, inv2 = 1.f / s2;

    // ---- pass 2: write w (streaming stores), accumulate out
    float* w_mm = out + OFF_W_MM + ((size_t)bh*SS + q)*SS;
    float* w_md = out + OFF_W_MD + ((size_t)bh*SS + q)*SS;
    float* w_dd = out + OFF_W_DD + ((size_t)bh*SS + q)*SS;
    const float4* gVm = g_mv + bh*SS;

    float4 o0 = make_float4(0,0,0,0), o1 = o0, o2 = o0;
    #pragma unroll 4
    for (int t = 0; t < 32; t++) {
        int k = t*32 + lane;
        float4 km = sKm[k];
        float4 kd = sKd[k];
        float addm = mrow[k] * NEGV;
        float l0 = 0.5f*(mq.x*km.x + mq.y*km.y + mq.z*km.z + mq.w*km.w) + addm;
        float l1 = 0.5f*(mq.x*kd.x + mq.y*kd.y + mq.z*kd.z + mq.w*kd.w) + addm;
        float l2 = 0.5f*(dq.x*kd.x + dq.y*kd.y + dq.z*kd.z + dq.w*kd.w) + addm;
        float mult = 1.0f - mcol[(size_t)k*SS];
        float w0 = __expf(l0 - m0) * inv0 * mult;
        float w1 = __expf(l1 - m1) * inv1 * mult;
        float w2 = __expf(l2 - m2) * inv2 * mult;
        __stcg(&w_mm[k], w0);
        __stcg(&w_md[k], w1);
        __stcg(&w_dd[k], w2);
        float4 vm = gVm[k];
        float4 vd = sVd[k];
        o0.x += w0*vm.x; o0.y += w0*vm.y; o0.z += w0*vm.z; o0.w += w0*vm.w;
        o1.x += w1*vd.x; o1.y += w1*vd.y; o1.z += w1*vd.z; o1.w += w1*vd.w;
        o2.x += w2*vd.x; o2.y += w2*vd.y; o2.z += w2*vd.z; o2.w += w2*vd.w;
    }
    #pragma unroll
    for (int off = 16; off > 0; off >>= 1) {
        o0.x += __shfl_xor_sync(0xffffffffu, o0.x, off);
        o0.y += __shfl_xor_sync(0xffffffffu, o0.y, off);
        o0.z += __shfl_xor_sync(0xffffffffu, o0.z, off);
        o0.w += __shfl_xor_sync(0xffffffffu, o0.w, off);
        o1.x += __shfl_xor_sync(0xffffffffu, o1.x, off);
        o1.y += __shfl_xor_sync(0xffffffffu, o1.y, off);
        o1.z += __shfl_xor_sync(0xffffffffu, o1.z, off);
        o1.w += __shfl_xor_sync(0xffffffffu, o1.w, off);
        o2.x += __shfl_xor_sync(0xffffffffu, o2.x, off);
        o2.y += __shfl_xor_sync(0xffffffffu, o2.y, off);
        o2.z += __shfl_xor_sync(0xffffffffu, o2.z, off);
        o2.w += __shfl_xor_sync(0xffffffffu, o2.w, off);
    }
    if (lane == 0) {
        g_att_mm[bh*SS + q] = o0;
        g_att_md[bh*SS + q] = o1;
        g_att_dd[bh*SS + q] = o2;
    }
}

// ============================================================================
// Kernel 3: merge heads + @wo + bo for the three small outputs.
// ============================================================================
__global__ void outproj_kernel(const float* __restrict__ wo, const float* __restrict__ bo,
                               float* __restrict__ out)
{
    __shared__ float swo[DD*DD];
    __shared__ float sbo[DD];
    int tid = threadIdx.x;
    for (int i = tid; i < DD*DD; i += blockDim.x) swo[i] = wo[i];
    if (tid < DD) sbo[tid] = bo[tid];
    __syncthreads();

    int row = blockIdx.x * blockDim.x + tid;   // b*S + s
    if (row >= BB*SS) return;
    int b = row / SS, s = row % SS;

    const float4* att[3] = {g_att_mm, g_att_md, g_att_dd};
    const size_t off[3] = {OFF_OUT_MM, OFF_OUT_MD, OFF_OUT_DD};

    #pragma unroll
    for (int a = 0; a < 3; a++) {
        float x[DD];
        #pragma unroll
        for (int h = 0; h < HH; h++) {
            float4 v = att[a][(b*HH + h)*SS + s];
            x[4*h]   = v.x; x[4*h+1] = v.y; x[4*h+2] = v.z; x[4*h+3] = v.w;
        }
        float* dst = out + off[a] + (size_t)row * DD;
        #pragma unroll
        for (int j = 0; j < DD; j++) {
            float acc = sbo[j];
            #pragma unroll
            for (int i = 0; i < DD; i++) acc += x[i] * swo[i*DD + j];
            dst[j] = acc;
        }
    }
}

// ============================================================================
extern "C" void kernel_launch(void* const* d_in, const int* in_sizes, int n_in,
                              void* d_out, int out_size)
{
    const float* med  = (const float*)d_in[0];
    const float* diag = (const float*)d_in[1];
    const float* mask = (const float*)d_in[2];
    const float* wmq = (const float*)d_in[3];
    const float* bmq = (const float*)d_in[4];
    const float* wmk = (const float*)d_in[5];
    const float* bmk = (const float*)d_in[6];
    const float* wmv = (const float*)d_in[7];
    const float* bmv = (const float*)d_in[8];
    const float* wdq = (const float*)d_in[9];
    const float* bdq = (const float*)d_in[10];
    const float* wdk = (const float*)d_in[11];
    const float* bdk = (const float*)d_in[12];
    const float* wdv = (const float*)d_in[13];
    const float* bdv = (const float*)d_in[14];
    const float* wo  = (const float*)d_in[15];
    const float* bo  = (const float*)d_in[16];
    float* out = (float*)d_out;

    proj_kernel<<<(2*BB*SS + 255)/256, 256>>>(med, diag,
        wmq, bmq, wmk, bmk, wmv, bmv, wdq, bdq, wdk, bdk, wdv, bdv);

    attn_kernel<<<dim3(SS/16, HH, BB), 512>>>(mask, out);

    outproj_kernel<<<(BB*SS + 255)/256, 256>>>(wo, bo, out);
}

// round 5
// speedup vs baseline: 1.6582x; 1.6582x over previous
#include <cuda_runtime.h>
#include <cstdint>
#include <cstddef>

#define BB 16
#define SS 1024
#define DD 16
#define HH 4
#define QSCALE 0.72134752044448170f /* 0.5 * log2(e)  */

// ---- output offsets (tuple order: out_mm, w_mm, out_md, w_md, out_dd, w_dd)
#define O_SZ (BB*SS*DD)
#define W_SZ ((size_t)BB*HH*SS*SS)
#define OFF_OUT_MM ((size_t)0)
#define OFF_W_MM   ((size_t)O_SZ)
#define OFF_OUT_MD (OFF_W_MM + W_SZ)
#define OFF_W_MD   (OFF_OUT_MD + O_SZ)
#define OFF_OUT_DD (OFF_W_MD + W_SZ)
#define OFF_W_DD   (OFF_OUT_DD + O_SZ)

// ---- scratch (__device__ globals; no allocations allowed)
__device__ float4 g_mq[BB*HH*SS], g_mk[BB*HH*SS], g_mv[BB*HH*SS];
__device__ float4 g_dq[BB*HH*SS], g_dk[BB*HH*SS], g_dv[BB*HH*SS];
__device__ float4 g_att_mm[BB*HH*SS], g_att_md[BB*HH*SS], g_att_dd[BB*HH*SS];

__device__ __forceinline__ float ex2(float x) {
    float y;
    asm("ex2.approx.ftz.f32 %0, %1;" : "=f"(y) : "f"(x));
    return y;
}

// ============================================================================
// Kernel 1: six 16x16 projections. Q outputs pre-scaled by 0.5*log2(e) so the
// attention kernel can use bare ex2 (no per-element multiply, no /sqrt(d)).
// ============================================================================
__global__ void proj_kernel(const float* __restrict__ med, const float* __restrict__ diag,
                            const float* __restrict__ wmq, const float* __restrict__ bmq,
                            const float* __restrict__ wmk, const float* __restrict__ bmk,
                            const float* __restrict__ wmv, const float* __restrict__ bmv,
                            const float* __restrict__ wdq, const float* __restrict__ bdq,
                            const float* __restrict__ wdk, const float* __restrict__ bdk,
                            const float* __restrict__ wdv, const float* __restrict__ bdv)
{
    __shared__ float sw[6][DD*DD];
    __shared__ float sb[6][DD];
    const float* wp[6] = {wmq, wmk, wmv, wdq, wdk, wdv};
    const float* bp[6] = {bmq, bmk, bmv, bdq, bdk, bdv};
    int tid = threadIdx.x;
    for (int w = 0; w < 6; w++) {
        for (int i = tid; i < DD*DD; i += blockDim.x) sw[w][i] = wp[w][i];
        if (tid < DD) sb[w][tid] = bp[w][tid];
    }
    __syncthreads();

    int gid = blockIdx.x * blockDim.x + tid;
    if (gid >= 2*BB*SS) return;
    int src = (gid >= BB*SS) ? 1 : 0;
    int row = gid - src*BB*SS;
    const float* x = (src ? diag : med) + (size_t)row * DD;

    float xv[DD];
    #pragma unroll
    for (int i = 0; i < DD; i++) xv[i] = x[i];

    const float* Wq = sw[src*3 + 0];
    const float* Wk = sw[src*3 + 1];
    const float* Wv = sw[src*3 + 2];
    const float* Bq = sb[src*3 + 0];
    const float* Bk = sb[src*3 + 1];
    const float* Bv = sb[src*3 + 2];

    float yq[DD], yk[DD], yv[DD];
    #pragma unroll
    for (int j = 0; j < DD; j++) {
        float aq = Bq[j], ak = Bk[j], av = Bv[j];
        #pragma unroll
        for (int i = 0; i < DD; i++) {
            float xi = xv[i];
            aq += xi * Wq[i*DD + j];
            ak += xi * Wk[i*DD + j];
            av += xi * Wv[i*DD + j];
        }
        yq[j] = aq * QSCALE;   // pre-scaled query
        yk[j] = ak; yv[j] = av;
    }

    int b = row / SS, s = row % SS;
    float4* Oq = src ? g_dq : g_mq;
    float4* Ok = src ? g_dk : g_mk;
    float4* Ov = src ? g_dv : g_mv;
    #pragma unroll
    for (int h = 0; h < HH; h++) {
        int idx = (b*HH + h)*SS + s;
        Oq[idx] = make_float4(yq[4*h], yq[4*h+1], yq[4*h+2], yq[4*h+3]);
        Ok[idx] = make_float4(yk[4*h], yk[4*h+1], yk[4*h+2], yk[4*h+3]);
        Ov[idx] = make_float4(yv[4*h], yv[4*h+1], yv[4*h+2], yv[4*h+3]);
    }
}

// ============================================================================
// Kernel 2: fused triple attention. Block = 16 q rows of one (b,h).
// Smem: K/V tiles (64KB) + packed 2-bit mask tile (20KB, stride-20 pad) +
// reduce scratch. Pass 1 (lane->q, K broadcast): unnormalized sums s and
// A*V accumulators o, max-free softmax. Pass 2 (warp=q, lane=k): recompute
// logits, write normalized masked weights with coalesced streaming stores.
// ============================================================================
#define MSTRIDE 20
__global__ __launch_bounds__(512, 2) void attn_kernel(const float* __restrict__ mask,
                                                      float* __restrict__ out)
{
    extern __shared__ unsigned char smem_raw[];
    float4*  sKm = (float4*)smem_raw;            // [1024]
    float4*  sKd = sKm + SS;                     // [1024]
    float4*  sVm = sKd + SS;                     // [1024]
    float4*  sVd = sVm + SS;                     // [1024]
    uint8_t* sM  = (uint8_t*)(sVd + SS);         // [1024][MSTRIDE]
    float*   sRed = (float*)(sM + SS*MSTRIDE);   // [16][16][17]
    float4*  sQm = (float4*)(sRed + 16*16*17);   // [16]
    float4*  sQd = sQm + 16;                     // [16]
    float*   sInv = (float*)(sQd + 16);          // [16][8]

    int qt = blockIdx.x, h = blockIdx.y, b = blockIdx.z;
    int bh = b*HH + h;
    int q0 = qt*16;
    int tid = threadIdx.x;
    int lane = tid & 31, warp = tid >> 5;

    // ---- stage K/V tiles (coalesced float4)
    for (int i = tid; i < SS; i += 512) {
        sKm[i] = g_mk[bh*SS + i];
        sKd[i] = g_dk[bh*SS + i];
        sVm[i] = g_mv[bh*SS + i];
        sVd[i] = g_dv[bh*SS + i];
    }
    if (tid < 16) { sQm[tid] = g_mq[bh*SS + q0 + tid]; sQd[tid] = g_dq[bh*SS + q0 + tid]; }

    // ---- stage additive-mask bit: sM[k][q] bit0 = (mask[b,q0+q,k] != 0)
    {
        int q = tid >> 5;           // warp -> q row
        const float* mrow = mask + ((size_t)b*SS + q0 + q)*SS;
        for (int k0 = 0; k0 < SS; k0 += 32) {
            int k = k0 + lane;      // coalesced 128B per warp
            sM[k*MSTRIDE + q] = (uint8_t)(mrow[k] != 0.0f ? 1u : 0u);
        }
    }
    __syncthreads();
    // ---- OR in mult-mask bit: bit1 = (mask[b,k,q0+q] != 0)
    {
        int q = tid & 15;
        int kk = tid >> 4;          // 32 k rows per sweep
        const float* mbase = mask + (size_t)b*SS*SS + q0 + q;
        for (int k0 = 0; k0 < SS; k0 += 32) {
            int k = k0 + kk;        // 16 threads read 64B contiguous per k-row
            float mv = mbase[(size_t)k*SS];
            uint8_t v = sM[k*MSTRIDE + q];
            sM[k*MSTRIDE + q] = v | (mv != 0.0f ? 2u : 0u);
        }
    }
    __syncthreads();

    // =================== Pass 1: sums + unnormalized A*V ===================
    {
        int q = lane & 15;
        int kpar = lane >> 4;
        float4 qm = sQm[q], qd = sQd[q];
        float s0 = 0.f, s1 = 0.f, s2 = 0.f;
        float4 o0 = make_float4(0,0,0,0), o1 = o0, o2 = o0;
        int kbase = warp*64 + kpar;
        #pragma unroll 4
        for (int j = 0; j < 32; j++) {
            int k = kbase + j*2;
            float4 km = sKm[k], kd = sKd[k];   // 2-address broadcast: 1 phase
            unsigned m = sM[k*MSTRIDE + q];
            float l0 = qm.x*km.x + qm.y*km.y + qm.z*km.z + qm.w*km.w;
            float l1 = qm.x*kd.x + qm.y*kd.y + qm.z*kd.z + qm.w*kd.w;
            float l2 = qd.x*kd.x + qd.y*kd.y + qd.z*kd.z + qd.w*kd.w;
            float e0 = ex2(l0), e1 = ex2(l1), e2 = ex2(l2);
            if (m & 1u) { e0 = 0.f; e1 = 0.f; e2 = 0.f; }
            s0 += e0; s1 += e1; s2 += e2;
            float u0 = (m & 2u) ? 0.f : e0;
            float u1 = (m & 2u) ? 0.f : e1;
            float u2 = (m & 2u) ? 0.f : e2;
            float4 vm = sVm[k], vd = sVd[k];
            o0.x += u0*vm.x; o0.y += u0*vm.y; o0.z += u0*vm.z; o0.w += u0*vm.w;
            o1.x += u1*vd.x; o1.y += u1*vd.y; o1.z += u1*vd.z; o1.w += u1*vd.w;
            o2.x += u2*vd.x; o2.y += u2*vd.y; o2.z += u2*vd.z; o2.w += u2*vd.w;
        }
        // combine k-parity partner (lane, lane+16 share q)
        const unsigned FULL = 0xffffffffu;
        s0 += __shfl_down_sync(FULL, s0, 16);
        s1 += __shfl_down_sync(FULL, s1, 16);
        s2 += __shfl_down_sync(FULL, s2, 16);
        o0.x += __shfl_down_sync(FULL, o0.x, 16); o0.y += __shfl_down_sync(FULL, o0.y, 16);
        o0.z += __shfl_down_sync(FULL, o0.z, 16); o0.w += __shfl_down_sync(FULL, o0.w, 16);
        o1.x += __shfl_down_sync(FULL, o1.x, 16); o1.y += __shfl_down_sync(FULL, o1.y, 16);
        o1.z += __shfl_down_sync(FULL, o1.z, 16); o1.w += __shfl_down_sync(FULL, o1.w, 16);
        o2.x += __shfl_down_sync(FULL, o2.x, 16); o2.y += __shfl_down_sync(FULL, o2.y, 16);
        o2.z += __shfl_down_sync(FULL, o2.z, 16); o2.w += __shfl_down_sync(FULL, o2.w, 16);
        if (lane < 16) {
            float* r = &sRed[(warp*16 + q)*17];
            r[0] = s0;   r[1] = s1;   r[2] = s2;
            r[3] = o0.x; r[4] = o0.y; r[5] = o0.z; r[6] = o0.w;
            r[7] = o1.x; r[8] = o1.y; r[9] = o1.z; r[10] = o1.w;
            r[11] = o2.x; r[12] = o2.y; r[13] = o2.z; r[14] = o2.w;
        }
    }
    __syncthreads();

    // ---- cross-warp reduce: warp `warp` owns q row = warp
    {
        float acc = 0.f;
        if (lane < 15) {
            #pragma unroll
            for (int w = 0; w < 16; w++) acc += sRed[(w*16 + warp)*17 + lane];
        }
        __syncwarp();
        const unsigned FULL = 0xffffffffu;
        float S0 = __shfl_sync(FULL, acc, 0);
        float S1 = __shfl_sync(FULL, acc, 1);
        float S2 = __shfl_sync(FULL, acc, 2);
        float inv0 = (S0 > 0.f) ? 1.0f/S0 : 0.f;
        float inv1 = (S1 > 0.f) ? 1.0f/S1 : 0.f;
        float inv2 = (S2 > 0.f) ? 1.0f/S2 : 0.f;
        float b0 = (S0 > 0.f) ? 0.f : (1.0f/1024.0f);
        float b1 = (S1 > 0.f) ? 0.f : (1.0f/1024.0f);
        float b2 = (S2 > 0.f) ? 0.f : (1.0f/1024.0f);
        if (lane == 0) {
            float* iv = &sInv[warp*8];
            iv[0] = inv0; iv[1] = inv1; iv[2] = inv2;
            iv[3] = b0;   iv[4] = b1;   iv[5] = b2;
        }
        if (lane >= 3 && lane < 15) {
            int slot = lane - 3;
            int att = slot >> 2, comp = slot & 3;
            float invsel = (att == 0) ? inv0 : ((att == 1) ? inv1 : inv2);
            float* basep = (att == 0) ? (float*)g_att_mm
                         : (att == 1) ? (float*)g_att_md : (float*)g_att_dd;
            basep[((size_t)bh*SS + q0 + warp)*4 + comp] = acc * invsel;
        }
    }
    __syncthreads();

    // =================== Pass 2: normalized weight stores ===================
    {
        int q = warp;                 // warp handles q row q0+warp
        float4 qm = sQm[q], qd = sQd[q];
        const float* iv = &sInv[q*8];
        float inv0 = iv[0], inv1 = iv[1], inv2 = iv[2];
        float b0 = iv[3], b1 = iv[4], b2 = iv[5];
        float* w_mm = out + OFF_W_MM + ((size_t)bh*SS + q0 + q)*SS;
        float* w_md = out + OFF_W_MD + ((size_t)bh*SS + q0 + q)*SS;
        float* w_dd = out + OFF_W_DD + ((size_t)bh*SS + q0 + q)*SS;
        #pragma unroll 2
        for (int t = 0; t < 32; t++) {
            int k = t*32 + lane;
            float4 km = sKm[k], kd = sKd[k];
            unsigned m = sM[k*MSTRIDE + q];
            float l0 = qm.x*km.x + qm.y*km.y + qm.z*km.z + qm.w*km.w;
            float l1 = qm.x*kd.x + qm.y*kd.y + qm.z*kd.z + qm.w*kd.w;
            float l2 = qd.x*kd.x + qd.y*kd.y + qd.z*kd.z + qd.w*kd.w;
            float e0 = ex2(l0), e1 = ex2(l1), e2 = ex2(l2);
            if (m & 1u) { e0 = 0.f; e1 = 0.f; e2 = 0.f; }
            float w0 = e0*inv0 + b0;
            float w1 = e1*inv1 + b1;
            float w2 = e2*inv2 + b2;
            if (m & 2u) { w0 = 0.f; w1 = 0.f; w2 = 0.f; }
            __stcg(w_mm + k, w0);
            __stcg(w_md + k, w1);
            __stcg(w_dd + k, w2);
        }
    }
}

// ============================================================================
// Kernel 3: merge heads + @wo + bo for the three small outputs.
// ============================================================================
__global__ void outproj_kernel(const float* __restrict__ wo, const float* __restrict__ bo,
                               float* __restrict__ out)
{
    __shared__ float swo[DD*DD];
    __shared__ float sbo[DD];
    int tid = threadIdx.x;
    for (int i = tid; i < DD*DD; i += blockDim.x) swo[i] = wo[i];
    if (tid < DD) sbo[tid] = bo[tid];
    __syncthreads();

    int row = blockIdx.x * blockDim.x + tid;
    if (row >= BB*SS) return;
    int b = row / SS, s = row % SS;

    const float4* att[3] = {g_att_mm, g_att_md, g_att_dd};
    const size_t off[3] = {OFF_OUT_MM, OFF_OUT_MD, OFF_OUT_DD};

    #pragma unroll
    for (int a = 0; a < 3; a++) {
        float x[DD];
        #pragma unroll
        for (int h = 0; h < HH; h++) {
            float4 v = att[a][(b*HH + h)*SS + s];
            x[4*h] = v.x; x[4*h+1] = v.y; x[4*h+2] = v.z; x[4*h+3] = v.w;
        }
        float* dst = out + off[a] + (size_t)row * DD;
        #pragma unroll
        for (int j = 0; j < DD; j++) {
            float acc = sbo[j];
            #pragma unroll
            for (int i = 0; i < DD; i++) acc += x[i] * swo[i*DD + j];
            dst[j] = acc;
        }
    }
}

// ============================================================================
extern "C" void kernel_launch(void* const* d_in, const int* in_sizes, int n_in,
                              void* d_out, int out_size)
{
    const float* med  = (const float*)d_in[0];
    const float* diag = (const float*)d_in[1];
    const float* mask = (const float*)d_in[2];
    const float* wmq = (const float*)d_in[3];
    const float* bmq = (const float*)d_in[4];
    const float* wmk = (const float*)d_in[5];
    const float* bmk = (const float*)d_in[6];
    const float* wmv = (const float*)d_in[7];
    const float* bmv = (const float*)d_in[8];
    const float* wdq = (const float*)d_in[9];
    const float* bdq = (const float*)d_in[10];
    const float* wdk = (const float*)d_in[11];
    const float* bdk = (const float*)d_in[12];
    const float* wdv = (const float*)d_in[13];
    const float* bdv = (const float*)d_in[14];
    const float* wo  = (const float*)d_in[15];
    const float* bo  = (const float*)d_in[16];
    float* out = (float*)d_out;

    const int ATTN_SMEM = 4*SS*16 + SS*MSTRIDE + 16*16*17*4 + 2*16*16 + 16*8*4;
    // Idempotent, non-stream-ordered; called unconditionally every invocation
    // (no static guards allowed by the harness rules).
    cudaFuncSetAttribute(attn_kernel, cudaFuncAttributeMaxDynamicSharedMemorySize,
                         ATTN_SMEM);

    proj_kernel<<<(2*BB*SS + 255)/256, 256>>>(med, diag,
        wmq, bmq, wmk, bmk, wmv, bmv, wdq, bdq, wdk, bdk, wdv, bdv);

    attn_kernel<<<dim3(SS/16, HH, BB), 512, ATTN_SMEM>>>(mask, out);

    outproj_kernel<<<(BB*SS + 255)/256, 256>>>(wo, bo, out);
}